// round 11
// baseline (speedup 1.0000x reference)
#include <cuda_runtime.h>
#include <math.h>
#include <stdint.h>

// Problem constants (fixed by setup_inputs)
#define HH 512
#define WW 512
#define HW (HH * WW)            // 262144
#define VV 64
#define V3 (VV * VV * VV)       // 262144
#define NB 32
#define NPIX (NB * HW)          // 8388608

// Reachability: d>0 && in-range forces cz = rint((d+2)*15.75) in [32,63].
// Scratch: [b][((cx*64+cy)*32 + (cz-32))] float4{count,r,g,b}; 64 MB.
// Lifecycle: zero (TMA, dirty L2) -> splat REDs (L2) -> finalize reads +
// DISCARDs (no writeback) -> scratch's DRAM backing stays zero forever.
#define SCR_PER_B (VV * VV * 32)     // 131072 (= 1<<17) entries per batch
#define NSCRATCH (NB * SCR_PER_B)    // 4194304 entries = 64 MB

__device__ __align__(128) float4 g_acc[NSCRATCH];

// ---- helpers ---------------------------------------------------------------
__device__ __forceinline__ uint32_t smem_u32(const void* p) {
    uint32_t a;
    asm("{ .reg .u64 t; cvta.to.shared.u64 t, %1; cvt.u32.u64 %0, t; }"
        : "=r"(a) : "l"(p));
    return a;
}
__device__ __forceinline__ void tma_bulk_store(void* gdst, uint32_t ssrc,
                                               uint32_t bytes) {
    asm volatile("cp.async.bulk.global.shared::cta.bulk_group [%0], [%1], %2;"
                 :: "l"(gdst), "r"(ssrc), "r"(bytes) : "memory");
}
__device__ __forceinline__ void tma_commit() {
    asm volatile("cp.async.bulk.commit_group;" ::: "memory");
}
__device__ __forceinline__ void tma_wait_read0() {
    asm volatile("cp.async.bulk.wait_group.read 0;" ::: "memory");
}
__device__ __forceinline__ void fence_async_shared() {
    asm volatile("fence.proxy.async.shared::cta;" ::: "memory");
}
__device__ __forceinline__ uint64_t pol_evict_first() {
    uint64_t p;
    asm("createpolicy.fractional.L2::evict_last.b64 %0, 0.0;" : "=l"(p));
    // NOTE: fraction 0.0 evict_last == plain; we want evict_first:
    asm("createpolicy.fractional.L2::evict_first.b64 %0, 1.0;" : "=l"(p));
    return p;
}
__device__ __forceinline__ float4 ldg_stream(const float* a, uint64_t pol) {
    float4 v;
    asm("ld.global.nc.L2::cache_hint.v4.f32 {%0,%1,%2,%3}, [%4], %5;"
        : "=f"(v.x), "=f"(v.y), "=f"(v.z), "=f"(v.w) : "l"(a), "l"(pol));
    return v;
}
__device__ __forceinline__ void ldg256(const float* p, float4& v0, float4& v1) {
    asm volatile("ld.global.v8.f32 {%0,%1,%2,%3,%4,%5,%6,%7}, [%8];"
                 : "=f"(v0.x), "=f"(v0.y), "=f"(v0.z), "=f"(v0.w),
                   "=f"(v1.x), "=f"(v1.y), "=f"(v1.z), "=f"(v1.w)
                 : "l"(p));
}

// -------------------------------------------------- zero scratch (TMA) ----
// CTA zeroes 16KB smem once, then 4 x 16KB bulk stores cover 64KB of scratch.
__global__ __launch_bounds__(256) void zero_scratch_kernel() {
    __shared__ __align__(128) float zbuf[4096];          // 16 KB
    for (int i = threadIdx.x; i < 4096; i += 256) zbuf[i] = 0.0f;
    fence_async_shared();
    __syncthreads();
    if (threadIdx.x == 0) {
        char* dst = (char*)g_acc + (size_t)blockIdx.x * 65536;
        uint32_t src = smem_u32(zbuf);
        tma_bulk_store(dst,         src, 16384);
        tma_bulk_store(dst + 16384, src, 16384);
        tma_bulk_store(dst + 32768, src, 16384);
        tma_bulk_store(dst + 49152, src, 16384);
        tma_commit();
        tma_wait_read0();          // smem must stay alive until TMA read done
    }
    __syncthreads();
}

// --------------------------------------------------------------- splat ----
__global__ __launch_bounds__(256) void splat_kernel(const float* __restrict__ rgbd) {
    int t = blockIdx.x * blockDim.x + threadIdx.x;
    if (t >= NPIX / 4) return;
    uint64_t pfirst = pol_evict_first();

    int idx = t << 2;                // first of 4 consecutive pixels
    int b = idx >> 18;               // / HW
    int p = idx & (HW - 1);          // % HW   (multiple of 4)
    int h = p >> 9;
    int w0 = p & (WW - 1);

    const float* base = rgbd + (size_t)b * (4 * HW);
    float4 d4 = ldg_stream(base + 3 * HW + p, pfirst);

    float dv[4] = {d4.x, d4.y, d4.z, d4.w};
    int   lin[4];
    bool  valid[4];
    bool  any = false;
    float yb = (float)h - 256.0f;    // fx=fy=256, cx=cy=256

    #pragma unroll
    for (int k = 0; k < 4; k++) {
        float d = dv[k];
        bool ok = (d > 0.0f) && (d < 10.0f) && isfinite(d);
        float x = ((float)(w0 + k) - 256.0f) * d * (1.0f / 256.0f);
        float y = yb * d * (1.0f / 256.0f);
        // rintf = round-half-even = jnp.round; 15.75 == 63/4 exactly, same
        // single rounding as ((p+2)/4)*63 in the reference.
        float fx_ = rintf((x + 2.0f) * 15.75f);
        float fy_ = rintf((y + 2.0f) * 15.75f);
        float fz_ = rintf((d + 2.0f) * 15.75f);
        ok = ok && (fx_ >= 0.0f) && (fx_ <= 63.0f)
                && (fy_ >= 0.0f) && (fy_ <= 63.0f)
                && (fz_ >= 32.0f) && (fz_ <= 63.0f);
        valid[k] = ok;
        any = any || ok;
        int cx = (int)fx_, cy = (int)fy_, cz = (int)fz_;
        lin[k] = (b << 17) + ((((cx << 6) | cy) << 5) | (cz - 32));
    }

    if (!any) return;

    float4 r4 = ldg_stream(base + 0 * HW + p, pfirst);
    float4 g4 = ldg_stream(base + 1 * HW + p, pfirst);
    float4 b4 = ldg_stream(base + 2 * HW + p, pfirst);
    float rv[4] = {r4.x, r4.y, r4.z, r4.w};
    float gv[4] = {g4.x, g4.y, g4.z, g4.w};
    float bv[4] = {b4.x, b4.y, b4.z, b4.w};

    #pragma unroll
    for (int k = 0; k < 4; k++) {
        if (valid[k]) {
            float* a = (float*)&g_acc[lin[k]];
            asm volatile("red.global.add.v4.f32 [%0], {%1,%2,%3,%4};"
                         :: "l"(a), "f"(1.0f), "f"(rv[k]), "f"(gv[k]),
                            "f"(bv[k]) : "memory");
        }
    }
}

// ------------------------------------------------------ finalize (TMA) ----
// Branch-free resolve: count==0 => sums exactly 0 => sum*rcp(max(count,1))==0.
__device__ __forceinline__ void resolve(float4 a, float& occ, float& r,
                                        float& g, float& b) {
    float inv;
    asm("rcp.approx.f32 %0, %1;" : "=f"(inv) : "f"(fmaxf(a.x, 1.0f)));
    occ = (a.x > 0.0f) ? 1.0f : 0.0f;
    r = a.y * inv;
    g = a.z * inv;
    b = a.w * inv;
}

// CTA per (b, cx): reads its contiguous 32KB scratch span (2048 entries,
// L2-resident), stages the full 4-channel [cy][cz] output image (4 x 16KB)
// in smem, and TMA-bulk-stores the 4 contiguous output spans. Scratch lines
// discarded (no writeback).
__global__ __launch_bounds__(256) void finalize_kernel(float* __restrict__ out) {
    extern __shared__ __align__(128) float smem[];   // 4 * 4096 floats = 64KB
    int c = blockIdx.x;
    int b = c >> 6;                    // batch
    int cx = c & 63;
    int t = threadIdx.x;

    int sbase = (b << 17) + (cx << 11);   // scratch entry base for this CTA
    int e0 = sbase + (t << 3);            // this thread's 8 entries (128B)

    const float* sp = (const float*)&g_acc[e0];
    float4 a[8];
    ldg256(sp,      a[0], a[1]);
    ldg256(sp + 8,  a[2], a[3]);
    ldg256(sp + 16, a[4], a[5]);
    ldg256(sp + 24, a[6], a[7]);

    float4 occ0, rr0, gg0, bb0, occ1, rr1, gg1, bb1;
    resolve(a[0], occ0.x, rr0.x, gg0.x, bb0.x);
    resolve(a[1], occ0.y, rr0.y, gg0.y, bb0.y);
    resolve(a[2], occ0.z, rr0.z, gg0.z, bb0.z);
    resolve(a[3], occ0.w, rr0.w, gg0.w, bb0.w);
    resolve(a[4], occ1.x, rr1.x, gg1.x, bb1.x);
    resolve(a[5], occ1.y, rr1.y, gg1.y, bb1.y);
    resolve(a[6], occ1.z, rr1.z, gg1.z, bb1.z);
    resolve(a[7], occ1.w, rr1.w, gg1.w, bb1.w);

    // Stage into smem image: ch chunk = 4096 floats [cy][cz].
    int cy = t >> 2;                   // 0..63
    int czo = (t & 3) << 3;            // 0,8,16,24
    float4 z = make_float4(0.f, 0.f, 0.f, 0.f);
    {
        float* row0 = smem + 0 * 4096 + (cy << 6);
        float* row1 = smem + 1 * 4096 + (cy << 6);
        float* row2 = smem + 2 * 4096 + (cy << 6);
        float* row3 = smem + 3 * 4096 + (cy << 6);
        // zero half: cz in [czo, czo+8)
        *(float4*)(row0 + czo) = z;  *(float4*)(row0 + czo + 4) = z;
        *(float4*)(row1 + czo) = z;  *(float4*)(row1 + czo + 4) = z;
        *(float4*)(row2 + czo) = z;  *(float4*)(row2 + czo + 4) = z;
        *(float4*)(row3 + czo) = z;  *(float4*)(row3 + czo + 4) = z;
        // occupied half: cz in [32+czo, 32+czo+8)
        *(float4*)(row0 + 32 + czo) = occ0; *(float4*)(row0 + 36 + czo) = occ1;
        *(float4*)(row1 + 32 + czo) = rr0;  *(float4*)(row1 + 36 + czo) = rr1;
        *(float4*)(row2 + 32 + czo) = gg0;  *(float4*)(row2 + 36 + czo) = gg1;
        *(float4*)(row3 + 32 + czo) = bb0;  *(float4*)(row3 + 36 + czo) = bb1;
    }

    // Drop this thread's dirty scratch line (values already consumed above).
    asm volatile("discard.global.L2 [%0], 128;" :: "l"(&g_acc[e0]) : "memory");

    fence_async_shared();
    __syncthreads();

    if (t == 0) {
        // out[b][ch][cx][cy][cz]: per-channel contiguous 4096-float span.
        float* ob = out + (size_t)b * (4 * V3) + ((size_t)cx << 12);
        uint32_t src = smem_u32(smem);
        tma_bulk_store(ob,          src,             16384);
        tma_bulk_store(ob + V3,     src + 16384,     16384);
        tma_bulk_store(ob + 2 * V3, src + 2 * 16384, 16384);
        tma_bulk_store(ob + 3 * V3, src + 3 * 16384, 16384);
        tma_commit();
        tma_wait_read0();          // smem must stay alive until TMA read done
    }
    __syncthreads();
}

extern "C" void kernel_launch(void* const* d_in, const int* in_sizes, int n_in,
                              void* d_out, int out_size) {
    const float* rgbd = (const float*)d_in[0];
    float* out = (float*)d_out;

    // Idempotent attribute set (host-side, no allocation).
    cudaFuncSetAttribute(finalize_kernel,
                         cudaFuncAttributeMaxDynamicSharedMemorySize, 65536);

    const int T = 256;
    zero_scratch_kernel<<<(NSCRATCH * 16) / 65536, T>>>();   // 1024 CTAs
    splat_kernel<<<(NPIX / 4) / T, T>>>(rgbd);
    finalize_kernel<<<NB * VV, T, 65536>>>(out);             // 2048 CTAs
}

// round 12
// speedup vs baseline: 1.0953x; 1.0953x over previous
#include <cuda_runtime.h>
#include <math.h>
#include <stdint.h>

// Problem constants (fixed by setup_inputs)
#define HH 512
#define WW 512
#define HW (HH * WW)            // 262144
#define VV 64
#define V3 (VV * VV * VV)       // 262144
#define NB 32
#define NPIX (NB * HW)          // 8388608

// Reachability: d>0 && in-range forces cz = rint((d+2)*15.75) in [32,63].
// Scratch: [b][((cx*64+cy)*32 + (cz-32))] float4{count,r,g,b}; 64 MB.
// Lifecycle: zero (TMA bulk fill -> dirty L2, 5.0 TB/s measured) -> splat
// REDs (L2) -> finalize reads + DISCARDs (no writeback) -> scratch's DRAM
// backing stays zero forever.
#define SCR_PER_B (VV * VV * 32)     // 131072 (= 1<<17) entries per batch
#define NSCRATCH (NB * SCR_PER_B)    // 4194304 entries = 64 MB

__device__ __align__(128) float4 g_acc[NSCRATCH];

// ---- helpers ---------------------------------------------------------------
__device__ __forceinline__ uint32_t smem_u32(const void* p) {
    uint32_t a;
    asm("{ .reg .u64 t; cvta.to.shared.u64 t, %1; cvt.u32.u64 %0, t; }"
        : "=r"(a) : "l"(p));
    return a;
}
__device__ __forceinline__ void tma_bulk_store(void* gdst, uint32_t ssrc,
                                               uint32_t bytes) {
    asm volatile("cp.async.bulk.global.shared::cta.bulk_group [%0], [%1], %2;"
                 :: "l"(gdst), "r"(ssrc), "r"(bytes) : "memory");
}
__device__ __forceinline__ void tma_commit() {
    asm volatile("cp.async.bulk.commit_group;" ::: "memory");
}
__device__ __forceinline__ void tma_wait_read0() {
    asm volatile("cp.async.bulk.wait_group.read 0;" ::: "memory");
}
__device__ __forceinline__ void fence_async_shared() {
    asm volatile("fence.proxy.async.shared::cta;" ::: "memory");
}
__device__ __forceinline__ uint64_t pol_evict_first() {
    uint64_t p;
    asm("createpolicy.fractional.L2::evict_first.b64 %0, 1.0;" : "=l"(p));
    return p;
}
__device__ __forceinline__ float4 ldg_stream(const float* a, uint64_t pol) {
    float4 v;
    asm("ld.global.nc.L2::cache_hint.v4.f32 {%0,%1,%2,%3}, [%4], %5;"
        : "=f"(v.x), "=f"(v.y), "=f"(v.z), "=f"(v.w) : "l"(a), "l"(pol));
    return v;
}
__device__ __forceinline__ void ldg256(const float* p, float4& v0, float4& v1) {
    asm volatile("ld.global.v8.f32 {%0,%1,%2,%3,%4,%5,%6,%7}, [%8];"
                 : "=f"(v0.x), "=f"(v0.y), "=f"(v0.z), "=f"(v0.w),
                   "=f"(v1.x), "=f"(v1.y), "=f"(v1.z), "=f"(v1.w)
                 : "l"(p));
}
__device__ __forceinline__ void stg256(float* p, float4 v0, float4 v1) {
    asm volatile("st.global.v8.f32 [%0], {%1,%2,%3,%4,%5,%6,%7,%8};"
                 :: "l"(p), "f"(v0.x), "f"(v0.y), "f"(v0.z), "f"(v0.w),
                    "f"(v1.x), "f"(v1.y), "f"(v1.z), "f"(v1.w)
                 : "memory");
}

// -------------------------------------------------- zero scratch (TMA) ----
// CTA zeroes 16KB smem once, then 4 x 16KB bulk stores cover 64KB of
// scratch. Bulk stores issued from 4 different warps to deepen the TMA
// queue; one collective wait at the end.
__global__ __launch_bounds__(256) void zero_scratch_kernel() {
    __shared__ __align__(128) float zbuf[4096];          // 16 KB
    for (int i = threadIdx.x; i < 4096; i += 256) zbuf[i] = 0.0f;
    fence_async_shared();
    __syncthreads();
    int wid = threadIdx.x >> 5;
    int lid = threadIdx.x & 31;
    if (wid < 4 && lid == 0) {
        char* dst = (char*)g_acc + (size_t)blockIdx.x * 65536 + wid * 16384;
        tma_bulk_store(dst, smem_u32(zbuf), 16384);
        tma_commit();
        tma_wait_read0();          // smem must stay alive until TMA read done
    }
    __syncthreads();
}

// --------------------------------------------------------------- splat ----
__global__ __launch_bounds__(256) void splat_kernel(const float* __restrict__ rgbd) {
    int t = blockIdx.x * blockDim.x + threadIdx.x;
    if (t >= NPIX / 4) return;
    uint64_t pfirst = pol_evict_first();

    int idx = t << 2;                // first of 4 consecutive pixels
    int b = idx >> 18;               // / HW
    int p = idx & (HW - 1);          // % HW   (multiple of 4)
    int h = p >> 9;
    int w0 = p & (WW - 1);

    const float* base = rgbd + (size_t)b * (4 * HW);
    float4 d4 = ldg_stream(base + 3 * HW + p, pfirst);

    float dv[4] = {d4.x, d4.y, d4.z, d4.w};
    int   lin[4];
    bool  valid[4];
    bool  any = false;
    float yb = (float)h - 256.0f;    // fx=fy=256, cx=cy=256

    #pragma unroll
    for (int k = 0; k < 4; k++) {
        float d = dv[k];
        bool ok = (d > 0.0f) && (d < 10.0f) && isfinite(d);
        float x = ((float)(w0 + k) - 256.0f) * d * (1.0f / 256.0f);
        float y = yb * d * (1.0f / 256.0f);
        // rintf = round-half-even = jnp.round; 15.75 == 63/4 exactly, same
        // single rounding as ((p+2)/4)*63 in the reference.
        float fx_ = rintf((x + 2.0f) * 15.75f);
        float fy_ = rintf((y + 2.0f) * 15.75f);
        float fz_ = rintf((d + 2.0f) * 15.75f);
        ok = ok && (fx_ >= 0.0f) && (fx_ <= 63.0f)
                && (fy_ >= 0.0f) && (fy_ <= 63.0f)
                && (fz_ >= 32.0f) && (fz_ <= 63.0f);
        valid[k] = ok;
        any = any || ok;
        int cx = (int)fx_, cy = (int)fy_, cz = (int)fz_;
        lin[k] = (b << 17) + ((((cx << 6) | cy) << 5) | (cz - 32));
    }

    if (!any) return;

    float4 r4 = ldg_stream(base + 0 * HW + p, pfirst);
    float4 g4 = ldg_stream(base + 1 * HW + p, pfirst);
    float4 b4 = ldg_stream(base + 2 * HW + p, pfirst);
    float rv[4] = {r4.x, r4.y, r4.z, r4.w};
    float gv[4] = {g4.x, g4.y, g4.z, g4.w};
    float bv[4] = {b4.x, b4.y, b4.z, b4.w};

    #pragma unroll
    for (int k = 0; k < 4; k++) {
        if (valid[k]) {
            float* a = (float*)&g_acc[lin[k]];
            asm volatile("red.global.add.v4.f32 [%0], {%1,%2,%3,%4};"
                         :: "l"(a), "f"(1.0f), "f"(rv[k]), "f"(gv[k]),
                            "f"(bv[k]) : "memory");
        }
    }
}

// ------------------------------------------------------------ finalize ----
// Branch-free resolve: count==0 => sums exactly 0 => sum*rcp(max(count,1))==0.
__device__ __forceinline__ void resolve(float4 a, float& occ, float& r,
                                        float& g, float& b) {
    float inv;
    asm("rcp.approx.f32 %0, %1;" : "=f"(inv) : "f"(fmaxf(a.x, 1.0f)));
    occ = (a.x > 0.0f) ? 1.0f : 0.0f;
    r = a.y * inv;
    g = a.z * inv;
    b = a.w * inv;
}

// R10's measured-best finalize: thread t owns ONE 128B scratch line (8
// entries, 32B-aligned pairs): 4 x LDG.256 in, 4 x STG.256 occupied half +
// 4 x STG.256 zero half out, then one discard (no writeback).
__global__ __launch_bounds__(256) void finalize_kernel(float* __restrict__ out) {
    int t = blockIdx.x * blockDim.x + threadIdx.x;
    if (t >= NSCRATCH / 8) return;

    int s = t << 3;                    // 8 contiguous entries (one 128B line)
    int b = s >> 17;                   // batch
    int sl = s & (SCR_PER_B - 1);      // ((cx*64+cy)*32 + (cz-32)), mult of 8

    const float* sp = (const float*)&g_acc[s];
    float4 a[8];
    ldg256(sp,      a[0], a[1]);
    ldg256(sp + 8,  a[2], a[3]);
    ldg256(sp + 16, a[4], a[5]);
    ldg256(sp + 24, a[6], a[7]);

    float4 occ0, rr0, gg0, bb0, occ1, rr1, gg1, bb1;
    resolve(a[0], occ0.x, rr0.x, gg0.x, bb0.x);
    resolve(a[1], occ0.y, rr0.y, gg0.y, bb0.y);
    resolve(a[2], occ0.z, rr0.z, gg0.z, bb0.z);
    resolve(a[3], occ0.w, rr0.w, gg0.w, bb0.w);
    resolve(a[4], occ1.x, rr1.x, gg1.x, bb1.x);
    resolve(a[5], occ1.y, rr1.y, gg1.y, bb1.y);
    resolve(a[6], occ1.z, rr1.z, gg1.z, bb1.z);
    resolve(a[7], occ1.w, rr1.w, gg1.w, bb1.w);

    int rhi = (sl >> 5) << 6;          // (cx*64+cy)*64
    int rocc = rhi + (sl & 31) + 32;   // occupied half (32B aligned)
    int rzer = rhi + (sl & 31);        // zero half (32B aligned)
    float* ob = out + (size_t)b * (4 * V3);
    float4 z = make_float4(0.f, 0.f, 0.f, 0.f);

    stg256(ob + rocc,          occ0, occ1);
    stg256(ob + V3 + rocc,     rr0,  rr1);
    stg256(ob + 2 * V3 + rocc, gg0,  gg1);
    stg256(ob + 3 * V3 + rocc, bb0,  bb1);

    stg256(ob + rzer,          z, z);
    stg256(ob + V3 + rzer,     z, z);
    stg256(ob + 2 * V3 + rzer, z, z);
    stg256(ob + 3 * V3 + rzer, z, z);

    // Drop the dirty scratch line without writeback (DRAM backing stays
    // zero; next call's zero_scratch redirties it in L2).
    asm volatile("discard.global.L2 [%0], 128;" :: "l"(&g_acc[s]) : "memory");
}

extern "C" void kernel_launch(void* const* d_in, const int* in_sizes, int n_in,
                              void* d_out, int out_size) {
    const float* rgbd = (const float*)d_in[0];
    float* out = (float*)d_out;

    const int T = 256;
    zero_scratch_kernel<<<(NSCRATCH * 16) / 65536, T>>>();   // 1024 CTAs
    splat_kernel<<<(NPIX / 4) / T, T>>>(rgbd);
    finalize_kernel<<<(NSCRATCH / 8) / T, T>>>(out);
}